// round 9
// baseline (speedup 1.0000x reference)
#include <cuda_runtime.h>
#include <cuda_bf16.h>
#include <math.h>
#include <stdint.h>

#define L_ 4
#define H_ 8
#define D_ 512
#define HD_ 64
#define F_ 2048
#define V_ 32000
#define B_ 2
#define S_ 2048
#define M_ (B_ * S_)
#define QKV_ (3 * D_)

typedef unsigned short u16;

// ---------------- scratch ----------------
__device__ float g_x[M_ * D_];
__device__ float g_qkv[M_ * QKV_];
__device__ float g_t[M_ * D_];
__device__ u16 g_xhi[M_ * D_], g_xlo[M_ * D_];
__device__ u16 g_ohi[M_ * D_], g_olo[M_ * D_];
__device__ u16 g_hhi[M_ * F_], g_hlo[M_ * F_];
__device__ u16 g_wqh[QKV_ * D_], g_wql[QKV_ * D_];
__device__ u16 g_woh[D_ * D_],  g_wol[D_ * D_];
__device__ u16 g_w1h[F_ * D_],  g_w1l[F_ * D_];
__device__ u16 g_w2h[D_ * F_],  g_w2l[D_ * F_];
__device__ u16 g_hwh[V_ * D_],  g_hwl[V_ * D_];

// ---------------- split helpers ----------------
__device__ __forceinline__ u16 bf_hi(float v) {
    return (u16)(__float_as_uint(v) >> 16);
}
__device__ __forceinline__ u16 bf_lo(float v) {
    float hi = __uint_as_float(__float_as_uint(v) & 0xFFFF0000u);
    __nv_bfloat16 l = __float2bfloat16_rn(v - hi);
    return *(u16*)&l;
}

__device__ __forceinline__ uint32_t smem_u32(const void* p) {
    uint32_t a;
    asm("{ .reg .u64 t; cvta.to.shared.u64 t, %1; cvt.u32.u64 %0, t; }"
        : "=r"(a) : "l"(p));
    return a;
}

// ==================== bf16 mma.sync GEMM (pre-split operands) ====================
// C[M,N] = (Ahi+Alo)[M,K] @ (Bhi+Blo)[N,K]^T, 3 passes, fp32 accum.
// CTA tile 128x256, 8 warps of 64x64, K-chunk 32, 3-stage cp.async.
#define KSTR 40
#define A_MAT (128 * KSTR * 2)   // 10240 B
#define B_MAT (256 * KSTR * 2)   // 20480 B
#define AH_OFF 0
#define AL_OFF A_MAT
#define BH_OFF (2 * A_MAT)
#define BL_OFF (2 * A_MAT + B_MAT)
#define STG_B  (2 * A_MAT + 2 * B_MAT)   // 61440
#define NSTG   3
#define SMEM_GEMM (NSTG * STG_B)         // 184320

#define CP16(s, g)   asm volatile("cp.async.cg.shared.global [%0], [%1], 16;" :: "r"(s), "l"(g))
#define CP_COMMIT()  asm volatile("cp.async.commit_group;" ::: "memory")
#define CP_WAIT(n)   asm volatile("cp.async.wait_group %0;" :: "n"(n) : "memory")

#define LDSM4(r, addr)                                                          \
    asm volatile("ldmatrix.sync.aligned.m8n8.x4.shared.b16 {%0,%1,%2,%3}, [%4];" \
                 : "=r"((r)[0]), "=r"((r)[1]), "=r"((r)[2]), "=r"((r)[3])        \
                 : "r"(addr))
#define MMA(c, a, b)                                                            \
    asm volatile("mma.sync.aligned.m16n8k16.row.col.f32.bf16.bf16.f32 "          \
                 "{%0,%1,%2,%3}, {%4,%5,%6,%7}, {%8,%9}, {%0,%1,%2,%3};"         \
                 : "+f"((c)[0]), "+f"((c)[1]), "+f"((c)[2]), "+f"((c)[3])        \
                 : "r"((a)[0]), "r"((a)[1]), "r"((a)[2]), "r"((a)[3]),           \
                   "r"((b)[0]), "r"((b)[1]))

template <bool SPLIT_OUT>
__global__ __launch_bounds__(256)
void gemm_bf16(const u16* __restrict__ Ahi, const u16* __restrict__ Alo,
               const u16* __restrict__ Bhi, const u16* __restrict__ Blo,
               const float* __restrict__ bias, float* __restrict__ Cf,
               u16* __restrict__ Chi, u16* __restrict__ Clo,
               int M, int N, int K, int relu) {
    extern __shared__ char sm[];
    uint32_t sb = smem_u32(sm);
    int tid = threadIdx.x, wid = tid >> 5, lane = tid & 31;
    int bm = blockIdx.y * 128, bn = blockIdx.x * 256;
    int warp_m = (wid & 1) * 64, warp_n = (wid >> 1) * 64;

    // ldmatrix lane bases (elem units)
    uint32_t a_base = (uint32_t)(warp_m + (lane & 15)) * KSTR + ((lane >> 4) << 3);
    uint32_t b_base = (uint32_t)(warp_n + ((lane >> 4) << 3) + (lane & 7)) * KSTR
                      + (((lane >> 3) & 1) << 3);

    float acc[4][8][4];
#pragma unroll
    for (int mi = 0; mi < 4; mi++)
#pragma unroll
        for (int nj = 0; nj < 8; nj++)
#pragma unroll
            for (int f = 0; f < 4; f++) acc[mi][nj][f] = 0.0f;

    int nt = K >> 5;

    auto load_stage = [&](int stg, int t) {
        uint32_t ss = sb + (uint32_t)stg * STG_B;
        int k0 = t << 5;
#pragma unroll
        for (int i = 0; i < 2; i++) {
            int c = i * 256 + tid;
            int row = c >> 2, q = c & 3;
            uint32_t so = row * (KSTR * 2) + q * 16;
            size_t ga = (size_t)(bm + row) * K + k0 + q * 8;
            CP16(ss + AH_OFF + so, &Ahi[ga]);
            CP16(ss + AL_OFF + so, &Alo[ga]);
        }
#pragma unroll
        for (int i = 0; i < 4; i++) {
            int c = i * 256 + tid;
            int row = c >> 2, q = c & 3;
            uint32_t so = row * (KSTR * 2) + q * 16;
            size_t gb = (size_t)(bn + row) * K + k0 + q * 8;
            CP16(ss + BH_OFF + so, &Bhi[gb]);
            CP16(ss + BL_OFF + so, &Blo[gb]);
        }
    };

    load_stage(0, 0); CP_COMMIT();
    load_stage(1, 1); CP_COMMIT();

    for (int t = 0; t < nt; t++) {
        CP_WAIT(1);
        __syncthreads();

        uint32_t sa = sb + (uint32_t)(t % NSTG) * STG_B;
#pragma unroll
        for (int ks = 0; ks < 2; ks++) {
            int kb = ks * 16;
            uint32_t ah[4][4], al[4][4], bh[4][4], bl[4][4];
#pragma unroll
            for (int mi = 0; mi < 4; mi++)
                LDSM4(ah[mi], sa + AH_OFF + (a_base + mi * 16 * KSTR + kb) * 2);
#pragma unroll
            for (int ni = 0; ni < 4; ni++)
                LDSM4(bh[ni], sa + BH_OFF + (b_base + ni * 16 * KSTR + kb) * 2);
#pragma unroll
            for (int mi = 0; mi < 4; mi++)
#pragma unroll
                for (int ni = 0; ni < 4; ni++) {
                    MMA(acc[mi][2 * ni],     ah[mi], &bh[ni][0]);
                    MMA(acc[mi][2 * ni + 1], ah[mi], &bh[ni][2]);
                }
#pragma unroll
            for (int mi = 0; mi < 4; mi++)
                LDSM4(al[mi], sa + AL_OFF + (a_base + mi * 16 * KSTR + kb) * 2);
#pragma unroll
            for (int mi = 0; mi < 4; mi++)
#pragma unroll
                for (int ni = 0; ni < 4; ni++) {
                    MMA(acc[mi][2 * ni],     al[mi], &bh[ni][0]);
                    MMA(acc[mi][2 * ni + 1], al[mi], &bh[ni][2]);
                }
#pragma unroll
            for (int ni = 0; ni < 4; ni++)
                LDSM4(bl[ni], sa + BL_OFF + (b_base + ni * 16 * KSTR + kb) * 2);
#pragma unroll
            for (int mi = 0; mi < 4; mi++)
#pragma unroll
                for (int ni = 0; ni < 4; ni++) {
                    MMA(acc[mi][2 * ni],     ah[mi], &bl[ni][0]);
                    MMA(acc[mi][2 * ni + 1], ah[mi], &bl[ni][2]);
                }
        }

        if (t + 2 < nt) load_stage((t + 2) % NSTG, t + 2);
        CP_COMMIT();
    }

    // epilogue
    int gid = lane >> 2, tig = lane & 3;
#pragma unroll
    for (int mi = 0; mi < 4; mi++) {
        int r0 = bm + warp_m + mi * 16 + gid;
#pragma unroll
        for (int nj = 0; nj < 8; nj++) {
            int cg = bn + warp_n + nj * 8 + tig * 2;
            float c0 = acc[mi][nj][0], c1 = acc[mi][nj][1];
            float c2 = acc[mi][nj][2], c3 = acc[mi][nj][3];
            if (bias) {
                float bx = bias[cg], by = bias[cg + 1];
                c0 += bx; c1 += by; c2 += bx; c3 += by;
            }
            if (relu) {
                c0 = fmaxf(c0, 0.0f); c1 = fmaxf(c1, 0.0f);
                c2 = fmaxf(c2, 0.0f); c3 = fmaxf(c3, 0.0f);
            }
            if (SPLIT_OUT) {
                size_t i0 = (size_t)r0 * N + cg, i1 = (size_t)(r0 + 8) * N + cg;
                *(uint32_t*)&Chi[i0] = (uint32_t)bf_hi(c0) | ((uint32_t)bf_hi(c1) << 16);
                *(uint32_t*)&Clo[i0] = (uint32_t)bf_lo(c0) | ((uint32_t)bf_lo(c1) << 16);
                *(uint32_t*)&Chi[i1] = (uint32_t)bf_hi(c2) | ((uint32_t)bf_hi(c3) << 16);
                *(uint32_t*)&Clo[i1] = (uint32_t)bf_lo(c2) | ((uint32_t)bf_lo(c3) << 16);
            } else {
                *(float2*)&Cf[(size_t)r0 * N + cg] = make_float2(c0, c1);
                *(float2*)&Cf[(size_t)(r0 + 8) * N + cg] = make_float2(c2, c3);
            }
        }
    }
}

// ---------------- embedding + PE (+ split) ----------------
__global__ void embed_kernel(const int* __restrict__ tokens,
                             const float* __restrict__ emb,
                             float* __restrict__ x,
                             u16* __restrict__ xhi, u16* __restrict__ xlo) {
    int i = blockIdx.x * blockDim.x + threadIdx.x;
    if (i >= M_ * D_) return;
    int m = i / D_, d = i % D_;
    int s = m % S_;
    int tok = tokens[m];
    float expo = (float)(d & ~1) * (-logf(10000.0f) / (float)D_);
    float ang = (float)s * expf(expo);
    float pe = (d & 1) ? cosf(ang) : sinf(ang);
    float v = emb[tok * D_ + d] + pe;
    x[i] = v;
    xhi[i] = bf_hi(v);
    xlo[i] = bf_lo(v);
}

// ---------------- repack QKV weights -> [3D][D] split ----------------
__global__ void repack_qkvT_split(const float* __restrict__ Wq,
                                  const float* __restrict__ Wk,
                                  const float* __restrict__ Wv,
                                  u16* __restrict__ whi, u16* __restrict__ wlo) {
    int i = blockIdx.x * blockDim.x + threadIdx.x;
    if (i >= D_ * D_) return;
    int n = i / D_, d = i % D_;
    int h = n / HD_, e = n % HD_;
    int src = h * D_ * HD_ + d * HD_ + e;
    float vq = Wq[src], vk = Wk[src], vv = Wv[src];
    size_t iq = (size_t)n * D_ + d;
    whi[iq] = bf_hi(vq); wlo[iq] = bf_lo(vq);
    whi[iq + (size_t)D_ * D_] = bf_hi(vk); wlo[iq + (size_t)D_ * D_] = bf_lo(vk);
    whi[iq + (size_t)2 * D_ * D_] = bf_hi(vv); wlo[iq + (size_t)2 * D_ * D_] = bf_lo(vv);
}

// ---------------- transpose + split ----------------
__global__ void transpose_split(const float* __restrict__ in,
                                u16* __restrict__ ohi, u16* __restrict__ olo,
                                int R, int C) {
    __shared__ float tile[32][33];
    int c0 = blockIdx.x * 32, r0 = blockIdx.y * 32;
    int x = threadIdx.x, y = threadIdx.y;
#pragma unroll
    for (int i = 0; i < 32; i += 8)
        tile[y + i][x] = in[(size_t)(r0 + y + i) * C + c0 + x];
    __syncthreads();
#pragma unroll
    for (int i = 0; i < 32; i += 8) {
        float v = tile[x][y + i];
        size_t idx = (size_t)(c0 + y + i) * R + r0 + x;
        ohi[idx] = bf_hi(v);
        olo[idx] = bf_lo(v);
    }
}

// ---------------- plain split (head_W) ----------------
__global__ void split_plain(const float* __restrict__ in,
                            u16* __restrict__ ohi, u16* __restrict__ olo, int n) {
    int i = blockIdx.x * blockDim.x + threadIdx.x;
    if (i >= n) return;
    float v = in[i];
    ohi[i] = bf_hi(v);
    olo[i] = bf_lo(v);
}

// ---------------- causal flash attention, 32-key subtile softmax ----------------
__global__ __launch_bounds__(128)
void attn_kernel(const float* __restrict__ qkv,
                 u16* __restrict__ ohi, u16* __restrict__ olo) {
    __shared__ float Ks[64][64];
    __shared__ float Vs[64][64];
    int bh = blockIdx.y;
    int b = bh / H_, h = bh % H_;
    int sq = blockIdx.x * 128 + threadIdx.x;
    int row = b * S_ + sq;

    const float* q = qkv;
    const float* k = qkv + D_;
    const float* v = qkv + 2 * D_;

    float qr[64];
#pragma unroll
    for (int d = 0; d < 64; d++) qr[d] = q[(size_t)row * QKV_ + h * HD_ + d];

    float mx = -1e30f, l = 0.0f;
    float acc[64];
#pragma unroll
    for (int d = 0; d < 64; d++) acc[d] = 0.0f;

    const float scale = 0.125f;
    int ntiles = blockIdx.x * 2 + 2;

    for (int t = 0; t < ntiles; t++) {
        for (int i = threadIdx.x; i < 64 * 16; i += 128) {
            int j = i >> 4, d4 = (i & 15) * 4;
            size_t krow = (size_t)(b * S_ + t * 64 + j) * QKV_ + h * HD_ + d4;
            *(float4*)&Ks[j][d4] = *(const float4*)&k[krow];
            *(float4*)&Vs[j][d4] = *(const float4*)&v[krow];
        }
        __syncthreads();

#pragma unroll
        for (int jb = 0; jb < 64; jb += 32) {
            int lim = sq - (t * 64 + jb);   // valid j: j <= lim
            if (lim < 0) continue;

            float s[32];
#pragma unroll
            for (int j = 0; j < 32; j++) {
                const float4* kp = (const float4*)&Ks[jb + j][0];
                float d0 = 0.0f, d1 = 0.0f;
#pragma unroll
                for (int d4 = 0; d4 < 16; d4 += 2) {
                    float4 kv0 = kp[d4], kv1 = kp[d4 + 1];
                    d0 += qr[d4 * 4 + 0] * kv0.x + qr[d4 * 4 + 1] * kv0.y +
                          qr[d4 * 4 + 2] * kv0.z + qr[d4 * 4 + 3] * kv0.w;
                    d1 += qr[d4 * 4 + 4] * kv1.x + qr[d4 * 4 + 5] * kv1.y +
                          qr[d4 * 4 + 6] * kv1.z + qr[d4 * 4 + 7] * kv1.w;
                }
                s[j] = (j <= lim) ? (d0 + d1) * scale : -1e30f;
            }

            float tm = -1e30f;
#pragma unroll
            for (int j = 0; j < 32; j++) tm = fmaxf(tm, s[j]);
            float mnew = fmaxf(mx, tm);
            float corr = __expf(mx - mnew);
            l *= corr;
#pragma unroll
            for (int d = 0; d < 64; d++) acc[d] *= corr;

#pragma unroll
            for (int j = 0; j < 32; j++) {
                float p = __expf(s[j] - mnew);
                l += p;
                const float4* vp = (const float4*)&Vs[jb + j][0];
#pragma unroll
                for (int d4 = 0; d4 < 16; d4++) {
                    float4 vv = vp[d4];
                    acc[d4 * 4 + 0] += p * vv.x;
                    acc[d4 * 4 + 1] += p * vv.y;
                    acc[d4 * 4 + 2] += p * vv.z;
                    acc[d4 * 4 + 3] += p * vv.w;
                }
            }
            mx = mnew;
        }
        __syncthreads();
    }
    float inv = 1.0f / l;
#pragma unroll
    for (int d = 0; d < 64; d++) {
        float val = acc[d] * inv;
        size_t idx = (size_t)row * D_ + h * HD_ + d;
        ohi[idx] = bf_hi(val);
        olo[idx] = bf_lo(val);
    }
}

// ---------------- residual + LayerNorm (+ split) ----------------
__global__ __launch_bounds__(128)
void ln_kernel(float* __restrict__ x, const float* __restrict__ delta,
               const float* __restrict__ gamma, const float* __restrict__ beta,
               u16* __restrict__ xhi, u16* __restrict__ xlo) {
    int row = blockIdx.x;
    int tid = threadIdx.x;
    __shared__ float red[128];

    float v[4];
    float s = 0.0f;
#pragma unroll
    for (int i = 0; i < 4; i++) {
        int d = i * 128 + tid;
        float t = x[(size_t)row * D_ + d];
        if (delta) t += delta[(size_t)row * D_ + d];
        v[i] = t;
        s += t;
    }
    red[tid] = s;
    __syncthreads();
    for (int off = 64; off > 0; off >>= 1) {
        if (tid < off) red[tid] += red[tid + off];
        __syncthreads();
    }
    float mean = red[0] * (1.0f / D_);
    __syncthreads();

    float s2 = 0.0f;
#pragma unroll
    for (int i = 0; i < 4; i++) {
        float dv = v[i] - mean;
        s2 += dv * dv;
    }
    red[tid] = s2;
    __syncthreads();
    for (int off = 64; off > 0; off >>= 1) {
        if (tid < off) red[tid] += red[tid + off];
        __syncthreads();
    }
    float var = red[0] * (1.0f / D_);
    float rstd = rsqrtf(var + 1e-5f);
#pragma unroll
    for (int i = 0; i < 4; i++) {
        int d = i * 128 + tid;
        float o = (v[i] - mean) * rstd * gamma[d] + beta[d];
        size_t idx = (size_t)row * D_ + d;
        x[idx] = o;
        xhi[idx] = bf_hi(o);
        xlo[idx] = bf_lo(o);
    }
}

// ---------------- launch ----------------
extern "C" void kernel_launch(void* const* d_in, const int* in_sizes, int n_in,
                              void* d_out, int out_size) {
    const int* tokens    = (const int*)d_in[0];
    const float* emb     = (const float*)d_in[1];
    const float* Wq      = (const float*)d_in[2];
    const float* Wk      = (const float*)d_in[3];
    const float* Wv      = (const float*)d_in[4];
    const float* Wo      = (const float*)d_in[5];
    const float* bo      = (const float*)d_in[6];
    const float* ln1_g   = (const float*)d_in[7];
    const float* ln1_b   = (const float*)d_in[8];
    const float* W1      = (const float*)d_in[9];
    const float* b1      = (const float*)d_in[10];
    const float* W2      = (const float*)d_in[11];
    const float* b2      = (const float*)d_in[12];
    const float* ln2_g   = (const float*)d_in[13];
    const float* ln2_b   = (const float*)d_in[14];
    const float* lnf_g   = (const float*)d_in[15];
    const float* lnf_b   = (const float*)d_in[16];
    const float* head_W  = (const float*)d_in[17];
    float* out = (float*)d_out;

    float *x, *qkv, *t;
    u16 *xhi, *xlo, *ohi, *olo, *hhi, *hlo;
    u16 *wqh, *wql, *woh, *wol, *w1h, *w1l, *w2h, *w2l, *hwh, *hwl;
    cudaGetSymbolAddress((void**)&x, g_x);
    cudaGetSymbolAddress((void**)&qkv, g_qkv);
    cudaGetSymbolAddress((void**)&t, g_t);
    cudaGetSymbolAddress((void**)&xhi, g_xhi);
    cudaGetSymbolAddress((void**)&xlo, g_xlo);
    cudaGetSymbolAddress((void**)&ohi, g_ohi);
    cudaGetSymbolAddress((void**)&olo, g_olo);
    cudaGetSymbolAddress((void**)&hhi, g_hhi);
    cudaGetSymbolAddress((void**)&hlo, g_hlo);
    cudaGetSymbolAddress((void**)&wqh, g_wqh);
    cudaGetSymbolAddress((void**)&wql, g_wql);
    cudaGetSymbolAddress((void**)&woh, g_woh);
    cudaGetSymbolAddress((void**)&wol, g_wol);
    cudaGetSymbolAddress((void**)&w1h, g_w1h);
    cudaGetSymbolAddress((void**)&w1l, g_w1l);
    cudaGetSymbolAddress((void**)&w2h, g_w2h);
    cudaGetSymbolAddress((void**)&w2l, g_w2l);
    cudaGetSymbolAddress((void**)&hwh, g_hwh);
    cudaGetSymbolAddress((void**)&hwl, g_hwl);

    cudaFuncSetAttribute(gemm_bf16<false>, cudaFuncAttributeMaxDynamicSharedMemorySize, SMEM_GEMM);
    cudaFuncSetAttribute(gemm_bf16<true>,  cudaFuncAttributeMaxDynamicSharedMemorySize, SMEM_GEMM);

    embed_kernel<<<(M_ * D_ + 255) / 256, 256>>>(tokens, emb, x, xhi, xlo);
    split_plain<<<(V_ * D_ + 255) / 256, 256>>>(head_W, hwh, hwl, V_ * D_);

    dim3 gQKV(QKV_ / 256, M_ / 128);
    dim3 gD(D_ / 256, M_ / 128);
    dim3 gF(F_ / 256, M_ / 128);
    dim3 gV(V_ / 256, M_ / 128);
    dim3 gAttn(S_ / 128, B_ * H_);
    dim3 tb(32, 8);

    for (int l = 0; l < L_; l++) {
        const float* Wq_l = Wq + (size_t)l * H_ * D_ * HD_;
        const float* Wk_l = Wk + (size_t)l * H_ * D_ * HD_;
        const float* Wv_l = Wv + (size_t)l * H_ * D_ * HD_;
        const float* Wo_l = Wo + (size_t)l * D_ * D_;
        const float* bo_l = bo + (size_t)l * D_;
        const float* W1_l = W1 + (size_t)l * D_ * F_;
        const float* b1_l = b1 + (size_t)l * F_;
        const float* W2_l = W2 + (size_t)l * F_ * D_;
        const float* b2_l = b2 + (size_t)l * D_;

        repack_qkvT_split<<<(D_ * D_ + 255) / 256, 256>>>(Wq_l, Wk_l, Wv_l, wqh, wql);
        transpose_split<<<dim3(D_ / 32, D_ / 32), tb>>>(Wo_l, woh, wol, D_, D_);
        transpose_split<<<dim3(F_ / 32, D_ / 32), tb>>>(W1_l, w1h, w1l, D_, F_);
        transpose_split<<<dim3(D_ / 32, F_ / 32), tb>>>(W2_l, w2h, w2l, F_, D_);

        gemm_bf16<false><<<gQKV, 256, SMEM_GEMM>>>(xhi, xlo, wqh, wql, nullptr,
                                                   qkv, nullptr, nullptr, M_, QKV_, D_, 0);

        attn_kernel<<<gAttn, 128>>>(qkv, ohi, olo);

        gemm_bf16<false><<<gD, 256, SMEM_GEMM>>>(ohi, olo, woh, wol, bo_l,
                                                 t, nullptr, nullptr, M_, D_, D_, 0);
        ln_kernel<<<M_, 128>>>(x, t, ln1_g + (size_t)l * D_, ln1_b + (size_t)l * D_, xhi, xlo);

        gemm_bf16<true><<<gF, 256, SMEM_GEMM>>>(xhi, xlo, w1h, w1l, b1_l,
                                                nullptr, hhi, hlo, M_, F_, D_, 1);
        gemm_bf16<false><<<gD, 256, SMEM_GEMM>>>(hhi, hlo, w2h, w2l, b2_l,
                                                 t, nullptr, nullptr, M_, D_, F_, 0);
        ln_kernel<<<M_, 128>>>(x, t, ln2_g + (size_t)l * D_, ln2_b + (size_t)l * D_, xhi, xlo);
    }

    ln_kernel<<<M_, 128>>>(x, nullptr, lnf_g, lnf_b, xhi, xlo);
    gemm_bf16<false><<<gV, 256, SMEM_GEMM>>>(xhi, xlo, hwh, hwl, nullptr,
                                             out, nullptr, nullptr, M_, V_, D_, 0);
}

// round 10
// speedup vs baseline: 1.0539x; 1.0539x over previous
#include <cuda_runtime.h>
#include <cuda_fp16.h>
#include <cuda_bf16.h>
#include <math.h>
#include <stdint.h>

#define L_ 4
#define H_ 8
#define D_ 512
#define HD_ 64
#define F_ 2048
#define V_ 32000
#define B_ 2
#define S_ 2048
#define M_ (B_ * S_)
#define QKV_ (3 * D_)

typedef unsigned short u16;

// ---------------- scratch ----------------
__device__ float g_x[M_ * D_];
__device__ float g_qkv[M_ * QKV_];
__device__ float g_t[M_ * D_];
__device__ u16 g_xhi[M_ * D_], g_xlo[M_ * D_];
__device__ u16 g_ohi[M_ * D_], g_olo[M_ * D_];
__device__ u16 g_hhi[M_ * F_], g_hlo[M_ * F_];
__device__ u16 g_wq[QKV_ * D_];
__device__ u16 g_wo[D_ * D_];
__device__ u16 g_w1[F_ * D_];
__device__ u16 g_w2[D_ * F_];
__device__ u16 g_hw[V_ * D_];

// ---------------- fp16 split helpers ----------------
__device__ __forceinline__ u16 f16_hi(float v) {
    __half h = __float2half_rn(v);
    return *(u16*)&h;
}
__device__ __forceinline__ u16 f16_lo(float v) {
    __half h = __float2half_rn(v);
    float r = v - __half2float(h);
    __half l = __float2half_rn(r);
    return *(u16*)&l;
}

__device__ __forceinline__ uint32_t smem_u32(const void* p) {
    uint32_t a;
    asm("{ .reg .u64 t; cvta.to.shared.u64 t, %1; cvt.u32.u64 %0, t; }"
        : "=r"(a) : "l"(p));
    return a;
}

// ==================== fp16 mma.sync GEMM (2-pass split-A) ====================
// C[M,N] = (Ahi+Alo)[M,K] @ Bh[N,K]^T, fp32 accum.
// 128x128 CTA tile, 8 warps of 64x32, K-chunk 32, cp.async 4-stage pipeline.
#define KSTRIDE 40
#define MAT_B  (128 * KSTRIDE * 2)     // 10240 B
#define AH_OFF 0
#define AL_OFF (1 * MAT_B)
#define BH_OFF (2 * MAT_B)
#define STG_B  (3 * MAT_B)             // 30720 B per stage
#define NSTG   4
#define SMEM_GEMM (NSTG * STG_B)       // 122880 B

#define CP16(s, g)  asm volatile("cp.async.cg.shared.global [%0], [%1], 16;" :: "r"(s), "l"(g))
#define CP_COMMIT() asm volatile("cp.async.commit_group;" ::: "memory")
#define CP_WAIT2()  asm volatile("cp.async.wait_group 2;" ::: "memory")

#define LDSM4(r, addr)                                                          \
    asm volatile("ldmatrix.sync.aligned.m8n8.x4.shared.b16 {%0,%1,%2,%3}, [%4];" \
                 : "=r"((r)[0]), "=r"((r)[1]), "=r"((r)[2]), "=r"((r)[3])        \
                 : "r"(addr))
#define LDSM2(r, addr)                                                          \
    asm volatile("ldmatrix.sync.aligned.m8n8.x2.shared.b16 {%0,%1}, [%2];"       \
                 : "=r"((r)[0]), "=r"((r)[1]) : "r"(addr))
#define MMAH(c, a, b)                                                           \
    asm volatile("mma.sync.aligned.m16n8k16.row.col.f32.f16.f16.f32 "            \
                 "{%0,%1,%2,%3}, {%4,%5,%6,%7}, {%8,%9}, {%0,%1,%2,%3};"         \
                 : "+f"((c)[0]), "+f"((c)[1]), "+f"((c)[2]), "+f"((c)[3])        \
                 : "r"((a)[0]), "r"((a)[1]), "r"((a)[2]), "r"((a)[3]),           \
                   "r"((b)[0]), "r"((b)[1]))

template <bool SPLIT_OUT>
__global__ __launch_bounds__(256)
void gemm_f16(const u16* __restrict__ Ahi, const u16* __restrict__ Alo,
              const u16* __restrict__ Bh,
              const float* __restrict__ bias, float* __restrict__ Cf,
              u16* __restrict__ Chi, u16* __restrict__ Clo,
              int M, int N, int K, int relu) {
    extern __shared__ char sm[];
    uint32_t sb = smem_u32(sm);
    int tid = threadIdx.x, wid = tid >> 5, lane = tid & 31;
    int bm = blockIdx.y * 128, bn = blockIdx.x * 128;
    int warp_m = (wid & 1) * 64, warp_n = (wid >> 1) * 32;

    uint32_t a_off = (uint32_t)(warp_m + (lane & 15)) * KSTRIDE + ((lane >> 4) << 3);
    uint32_t b_off = (uint32_t)(warp_n + (lane & 7)) * KSTRIDE + (((lane >> 3) & 1) << 3);

    // cp.async mapping: 512 16B-chunks per matrix, 2 per thread per matrix
    int c0i = tid * 2;
    int lrow0 = c0i >> 2, lc0 = (c0i & 3);
    int lrow1 = (c0i + 1) >> 2, lc1 = ((c0i + 1) & 3);

    float acc[4][4][4];
#pragma unroll
    for (int mi = 0; mi < 4; mi++)
#pragma unroll
        for (int ni = 0; ni < 4; ni++)
#pragma unroll
            for (int f = 0; f < 4; f++) acc[mi][ni][f] = 0.0f;

    int nt = K >> 5;

    auto load_stage = [&](int stg, int t) {
        uint32_t ss = sb + (uint32_t)stg * STG_B;
        int k0 = t << 5;
        uint32_t s0 = lrow0 * (KSTRIDE * 2) + lc0 * 16;
        uint32_t s1 = lrow1 * (KSTRIDE * 2) + lc1 * 16;
        size_t ga0 = (size_t)(bm + lrow0) * K + k0 + lc0 * 8;
        size_t ga1 = (size_t)(bm + lrow1) * K + k0 + lc1 * 8;
        size_t gb0 = (size_t)(bn + lrow0) * K + k0 + lc0 * 8;
        size_t gb1 = (size_t)(bn + lrow1) * K + k0 + lc1 * 8;
        CP16(ss + AH_OFF + s0, &Ahi[ga0]);
        CP16(ss + AH_OFF + s1, &Ahi[ga1]);
        CP16(ss + AL_OFF + s0, &Alo[ga0]);
        CP16(ss + AL_OFF + s1, &Alo[ga1]);
        CP16(ss + BH_OFF + s0, &Bh[gb0]);
        CP16(ss + BH_OFF + s1, &Bh[gb1]);
    };

#pragma unroll
    for (int s = 0; s < NSTG - 1; s++) {
        if (s < nt) load_stage(s, s);
        CP_COMMIT();
    }

    for (int t = 0; t < nt; t++) {
        CP_WAIT2();
        __syncthreads();

        uint32_t sa = sb + (uint32_t)(t & (NSTG - 1)) * STG_B;
#pragma unroll
        for (int ks = 0; ks < 2; ks++) {
            uint32_t aoff2 = (a_off + ks * 16) * 2;
            uint32_t boff2 = (b_off + ks * 16) * 2;
            uint32_t ah[4][4], al[4][4], bh[4][2];
#pragma unroll
            for (int mi = 0; mi < 4; mi++)
                LDSM4(ah[mi], sa + AH_OFF + aoff2 + mi * (16 * KSTRIDE * 2));
#pragma unroll
            for (int ni = 0; ni < 4; ni++)
                LDSM2(bh[ni], sa + BH_OFF + boff2 + ni * (8 * KSTRIDE * 2));
#pragma unroll
            for (int mi = 0; mi < 4; mi++)
#pragma unroll
                for (int ni = 0; ni < 4; ni++) MMAH(acc[mi][ni], ah[mi], bh[ni]);
#pragma unroll
            for (int mi = 0; mi < 4; mi++)
                LDSM4(al[mi], sa + AL_OFF + aoff2 + mi * (16 * KSTRIDE * 2));
#pragma unroll
            for (int mi = 0; mi < 4; mi++)
#pragma unroll
                for (int ni = 0; ni < 4; ni++) MMAH(acc[mi][ni], al[mi], bh[ni]);
        }

        if (t + NSTG - 1 < nt) load_stage((t + NSTG - 1) & (NSTG - 1), t + NSTG - 1);
        CP_COMMIT();
    }

    // epilogue
    int gid = lane >> 2, tig = lane & 3;
#pragma unroll
    for (int mi = 0; mi < 4; mi++) {
        int r0 = bm + warp_m + mi * 16 + gid;
#pragma unroll
        for (int ni = 0; ni < 4; ni++) {
            int cg = bn + warp_n + ni * 8 + tig * 2;
            float c0 = acc[mi][ni][0], c1 = acc[mi][ni][1];
            float c2 = acc[mi][ni][2], c3 = acc[mi][ni][3];
            if (bias) {
                float bx = bias[cg], by = bias[cg + 1];
                c0 += bx; c1 += by; c2 += bx; c3 += by;
            }
            if (relu) {
                c0 = fmaxf(c0, 0.0f); c1 = fmaxf(c1, 0.0f);
                c2 = fmaxf(c2, 0.0f); c3 = fmaxf(c3, 0.0f);
            }
            if (SPLIT_OUT) {
                size_t i0 = (size_t)r0 * N + cg, i1 = (size_t)(r0 + 8) * N + cg;
                *(uint32_t*)&Chi[i0] = (uint32_t)f16_hi(c0) | ((uint32_t)f16_hi(c1) << 16);
                *(uint32_t*)&Clo[i0] = (uint32_t)f16_lo(c0) | ((uint32_t)f16_lo(c1) << 16);
                *(uint32_t*)&Chi[i1] = (uint32_t)f16_hi(c2) | ((uint32_t)f16_hi(c3) << 16);
                *(uint32_t*)&Clo[i1] = (uint32_t)f16_lo(c2) | ((uint32_t)f16_lo(c3) << 16);
            } else {
                *(float2*)&Cf[(size_t)r0 * N + cg] = make_float2(c0, c1);
                *(float2*)&Cf[(size_t)(r0 + 8) * N + cg] = make_float2(c2, c3);
            }
        }
    }
}

// ---------------- embedding + PE (+ split) ----------------
__global__ void embed_kernel(const int* __restrict__ tokens,
                             const float* __restrict__ emb,
                             float* __restrict__ x,
                             u16* __restrict__ xhi, u16* __restrict__ xlo) {
    int i = blockIdx.x * blockDim.x + threadIdx.x;
    if (i >= M_ * D_) return;
    int m = i / D_, d = i % D_;
    int s = m % S_;
    int tok = tokens[m];
    float expo = (float)(d & ~1) * (-logf(10000.0f) / (float)D_);
    float ang = (float)s * expf(expo);
    float pe = (d & 1) ? cosf(ang) : sinf(ang);
    float v = emb[tok * D_ + d] + pe;
    x[i] = v;
    xhi[i] = f16_hi(v);
    xlo[i] = f16_lo(v);
}

// ---------------- repack QKV weights -> [3D][D] fp16 ----------------
__global__ void repack_qkvT_h(const float* __restrict__ Wq,
                              const float* __restrict__ Wk,
                              const float* __restrict__ Wv,
                              u16* __restrict__ w) {
    int i = blockIdx.x * blockDim.x + threadIdx.x;
    if (i >= D_ * D_) return;
    int n = i / D_, d = i % D_;
    int h = n / HD_, e = n % HD_;
    int src = h * D_ * HD_ + d * HD_ + e;
    size_t iq = (size_t)n * D_ + d;
    w[iq] = f16_hi(Wq[src]);
    w[iq + (size_t)D_ * D_] = f16_hi(Wk[src]);
    w[iq + (size_t)2 * D_ * D_] = f16_hi(Wv[src]);
}

// ---------------- transpose to fp16: out[C][R] = h(in[R][C]) ----------------
__global__ void transpose_h(const float* __restrict__ in,
                            u16* __restrict__ o, int R, int C) {
    __shared__ float tile[32][33];
    int c0 = blockIdx.x * 32, r0 = blockIdx.y * 32;
    int x = threadIdx.x, y = threadIdx.y;
#pragma unroll
    for (int i = 0; i < 32; i += 8)
        tile[y + i][x] = in[(size_t)(r0 + y + i) * C + c0 + x];
    __syncthreads();
#pragma unroll
    for (int i = 0; i < 32; i += 8)
        o[(size_t)(c0 + y + i) * R + r0 + x] = f16_hi(tile[x][y + i]);
}

// ---------------- plain fp16 convert (head_W) ----------------
__global__ void conv_h(const float* __restrict__ in, u16* __restrict__ o, int n) {
    int i = blockIdx.x * blockDim.x + threadIdx.x;
    if (i >= n) return;
    o[i] = f16_hi(in[i]);
}

// ---------------- causal flash attention, 32-key subtile softmax ----------------
__global__ __launch_bounds__(128)
void attn_kernel(const float* __restrict__ qkv,
                 u16* __restrict__ ohi, u16* __restrict__ olo) {
    __shared__ float Ks[64][64];
    __shared__ float Vs[64][64];
    int bh = blockIdx.y;
    int b = bh / H_, h = bh % H_;
    int sq = blockIdx.x * 128 + threadIdx.x;
    int row = b * S_ + sq;

    const float* q = qkv;
    const float* k = qkv + D_;
    const float* v = qkv + 2 * D_;

    float qr[64];
#pragma unroll
    for (int d = 0; d < 64; d++) qr[d] = q[(size_t)row * QKV_ + h * HD_ + d];

    float mx = -1e30f, l = 0.0f;
    float acc[64];
#pragma unroll
    for (int d = 0; d < 64; d++) acc[d] = 0.0f;

    const float scale = 0.125f;
    int ntiles = blockIdx.x * 2 + 2;

    for (int t = 0; t < ntiles; t++) {
        for (int i = threadIdx.x; i < 64 * 16; i += 128) {
            int j = i >> 4, d4 = (i & 15) * 4;
            size_t krow = (size_t)(b * S_ + t * 64 + j) * QKV_ + h * HD_ + d4;
            *(float4*)&Ks[j][d4] = *(const float4*)&k[krow];
            *(float4*)&Vs[j][d4] = *(const float4*)&v[krow];
        }
        __syncthreads();

#pragma unroll
        for (int jb = 0; jb < 64; jb += 32) {
            int lim = sq - (t * 64 + jb);
            if (lim < 0) continue;

            float s[32];
#pragma unroll
            for (int j = 0; j < 32; j++) {
                const float4* kp = (const float4*)&Ks[jb + j][0];
                float d0 = 0.0f, d1 = 0.0f;
#pragma unroll
                for (int d4 = 0; d4 < 16; d4 += 2) {
                    float4 kv0 = kp[d4], kv1 = kp[d4 + 1];
                    d0 += qr[d4 * 4 + 0] * kv0.x + qr[d4 * 4 + 1] * kv0.y +
                          qr[d4 * 4 + 2] * kv0.z + qr[d4 * 4 + 3] * kv0.w;
                    d1 += qr[d4 * 4 + 4] * kv1.x + qr[d4 * 4 + 5] * kv1.y +
                          qr[d4 * 4 + 6] * kv1.z + qr[d4 * 4 + 7] * kv1.w;
                }
                s[j] = (j <= lim) ? (d0 + d1) * scale : -1e30f;
            }

            float tm = -1e30f;
#pragma unroll
            for (int j = 0; j < 32; j++) tm = fmaxf(tm, s[j]);
            float mnew = fmaxf(mx, tm);
            float corr = __expf(mx - mnew);
            l *= corr;
#pragma unroll
            for (int d = 0; d < 64; d++) acc[d] *= corr;

#pragma unroll
            for (int j = 0; j < 32; j++) {
                float p = __expf(s[j] - mnew);
                l += p;
                const float4* vp = (const float4*)&Vs[jb + j][0];
#pragma unroll
                for (int d4 = 0; d4 < 16; d4++) {
                    float4 vv = vp[d4];
                    acc[d4 * 4 + 0] += p * vv.x;
                    acc[d4 * 4 + 1] += p * vv.y;
                    acc[d4 * 4 + 2] += p * vv.z;
                    acc[d4 * 4 + 3] += p * vv.w;
                }
            }
            mx = mnew;
        }
        __syncthreads();
    }
    float inv = 1.0f / l;
#pragma unroll
    for (int d = 0; d < 64; d++) {
        float val = acc[d] * inv;
        size_t idx = (size_t)row * D_ + h * HD_ + d;
        ohi[idx] = f16_hi(val);
        olo[idx] = f16_lo(val);
    }
}

// ---------------- residual + LayerNorm (+ split) ----------------
__global__ __launch_bounds__(128)
void ln_kernel(float* __restrict__ x, const float* __restrict__ delta,
               const float* __restrict__ gamma, const float* __restrict__ beta,
               u16* __restrict__ xhi, u16* __restrict__ xlo) {
    int row = blockIdx.x;
    int tid = threadIdx.x;
    __shared__ float red[128];

    float v[4];
    float s = 0.0f;
#pragma unroll
    for (int i = 0; i < 4; i++) {
        int d = i * 128 + tid;
        float t = x[(size_t)row * D_ + d];
        if (delta) t += delta[(size_t)row * D_ + d];
        v[i] = t;
        s += t;
    }
    red[tid] = s;
    __syncthreads();
    for (int off = 64; off > 0; off >>= 1) {
        if (tid < off) red[tid] += red[tid + off];
        __syncthreads();
    }
    float mean = red[0] * (1.0f / D_);
    __syncthreads();

    float s2 = 0.0f;
#pragma unroll
    for (int i = 0; i < 4; i++) {
        float dv = v[i] - mean;
        s2 += dv * dv;
    }
    red[tid] = s2;
    __syncthreads();
    for (int off = 64; off > 0; off >>= 1) {
        if (tid < off) red[tid] += red[tid + off];
        __syncthreads();
    }
    float var = red[0] * (1.0f / D_);
    float rstd = rsqrtf(var + 1e-5f);
#pragma unroll
    for (int i = 0; i < 4; i++) {
        int d = i * 128 + tid;
        float o = (v[i] - mean) * rstd * gamma[d] + beta[d];
        size_t idx = (size_t)row * D_ + d;
        x[idx] = o;
        xhi[idx] = f16_hi(o);
        xlo[idx] = f16_lo(o);
    }
}

// ---------------- launch ----------------
extern "C" void kernel_launch(void* const* d_in, const int* in_sizes, int n_in,
                              void* d_out, int out_size) {
    const int* tokens    = (const int*)d_in[0];
    const float* emb     = (const float*)d_in[1];
    const float* Wq      = (const float*)d_in[2];
    const float* Wk      = (const float*)d_in[3];
    const float* Wv      = (const float*)d_in[4];
    const float* Wo      = (const float*)d_in[5];
    const float* bo      = (const float*)d_in[6];
    const float* ln1_g   = (const float*)d_in[7];
    const float* ln1_b   = (const float*)d_in[8];
    const float* W1      = (const float*)d_in[9];
    const float* b1      = (const float*)d_in[10];
    const float* W2      = (const float*)d_in[11];
    const float* b2      = (const float*)d_in[12];
    const float* ln2_g   = (const float*)d_in[13];
    const float* ln2_b   = (const float*)d_in[14];
    const float* lnf_g   = (const float*)d_in[15];
    const float* lnf_b   = (const float*)d_in[16];
    const float* head_W  = (const float*)d_in[17];
    float* out = (float*)d_out;

    float *x, *qkv, *t;
    u16 *xhi, *xlo, *ohi, *olo, *hhi, *hlo;
    u16 *wq, *wo, *w1, *w2, *hw;
    cudaGetSymbolAddress((void**)&x, g_x);
    cudaGetSymbolAddress((void**)&qkv, g_qkv);
    cudaGetSymbolAddress((void**)&t, g_t);
    cudaGetSymbolAddress((void**)&xhi, g_xhi);
    cudaGetSymbolAddress((void**)&xlo, g_xlo);
    cudaGetSymbolAddress((void**)&ohi, g_ohi);
    cudaGetSymbolAddress((void**)&olo, g_olo);
    cudaGetSymbolAddress((void**)&hhi, g_hhi);
    cudaGetSymbolAddress((void**)&hlo, g_hlo);
    cudaGetSymbolAddress((void**)&wq, g_wq);
    cudaGetSymbolAddress((void**)&wo, g_wo);
    cudaGetSymbolAddress((void**)&w1, g_w1);
    cudaGetSymbolAddress((void**)&w2, g_w2);
    cudaGetSymbolAddress((void**)&hw, g_hw);

    cudaFuncSetAttribute(gemm_f16<false>, cudaFuncAttributeMaxDynamicSharedMemorySize, SMEM_GEMM);
    cudaFuncSetAttribute(gemm_f16<true>,  cudaFuncAttributeMaxDynamicSharedMemorySize, SMEM_GEMM);

    embed_kernel<<<(M_ * D_ + 255) / 256, 256>>>(tokens, emb, x, xhi, xlo);
    conv_h<<<(V_ * D_ + 255) / 256, 256>>>(head_W, hw, V_ * D_);

    dim3 gQKV(QKV_ / 128, M_ / 128);
    dim3 gD(D_ / 128, M_ / 128);
    dim3 gF(F_ / 128, M_ / 128);
    dim3 gV(V_ / 128, M_ / 128);
    dim3 gAttn(S_ / 128, B_ * H_);
    dim3 tb(32, 8);

    for (int l = 0; l < L_; l++) {
        const float* Wq_l = Wq + (size_t)l * H_ * D_ * HD_;
        const float* Wk_l = Wk + (size_t)l * H_ * D_ * HD_;
        const float* Wv_l = Wv + (size_t)l * H_ * D_ * HD_;
        const float* Wo_l = Wo + (size_t)l * D_ * D_;
        const float* bo_l = bo + (size_t)l * D_;
        const float* W1_l = W1 + (size_t)l * D_ * F_;
        const float* b1_l = b1 + (size_t)l * F_;
        const float* W2_l = W2 + (size_t)l * F_ * D_;
        const float* b2_l = b2 + (size_t)l * D_;

        repack_qkvT_h<<<(D_ * D_ + 255) / 256, 256>>>(Wq_l, Wk_l, Wv_l, wq);
        transpose_h<<<dim3(D_ / 32, D_ / 32), tb>>>(Wo_l, wo, D_, D_);
        transpose_h<<<dim3(F_ / 32, D_ / 32), tb>>>(W1_l, w1, D_, F_);
        transpose_h<<<dim3(D_ / 32, F_ / 32), tb>>>(W2_l, w2, F_, D_);

        gemm_f16<false><<<gQKV, 256, SMEM_GEMM>>>(xhi, xlo, wq, nullptr,
                                                  qkv, nullptr, nullptr, M_, QKV_, D_, 0);

        attn_kernel<<<gAttn, 128>>>(qkv, ohi, olo);

        gemm_f16<false><<<gD, 256, SMEM_GEMM>>>(ohi, olo, wo, bo_l,
                                                t, nullptr, nullptr, M_, D_, D_, 0);
        ln_kernel<<<M_, 128>>>(x, t, ln1_g + (size_t)l * D_, ln1_b + (size_t)l * D_, xhi, xlo);

        gemm_f16<true><<<gF, 256, SMEM_GEMM>>>(xhi, xlo, w1, b1_l,
                                               nullptr, hhi, hlo, M_, F_, D_, 1);
        gemm_f16<false><<<gD, 256, SMEM_GEMM>>>(hhi, hlo, w2, b2_l,
                                                t, nullptr, nullptr, M_, D_, F_, 0);
        ln_kernel<<<M_, 128>>>(x, t, ln2_g + (size_t)l * D_, ln2_b + (size_t)l * D_, xhi, xlo);
    }

    ln_kernel<<<M_, 128>>>(x, nullptr, lnf_g, lnf_b, xhi, xlo);
    gemm_f16<false><<<gV, 256, SMEM_GEMM>>>(xhi, xlo, hw, nullptr,
                                            out, nullptr, nullptr, M_, V_, D_, 0);
}

// round 12
// speedup vs baseline: 2.6000x; 2.4670x over previous
#include <cuda_runtime.h>
#include <cuda_fp16.h>
#include <cuda_bf16.h>
#include <math.h>
#include <stdint.h>

#define L_ 4
#define H_ 8
#define D_ 512
#define HD_ 64
#define F_ 2048
#define V_ 32000
#define B_ 2
#define S_ 2048
#define M_ (B_ * S_)
#define QKV_ (3 * D_)

typedef unsigned short u16;

// ---------------- scratch ----------------
__device__ float g_x[M_ * D_];
__device__ float g_qkv[M_ * QKV_];
__device__ float g_t[M_ * D_];
__device__ u16 g_xhi[M_ * D_], g_xlo[M_ * D_];
__device__ u16 g_ohi[M_ * D_], g_olo[M_ * D_];
__device__ u16 g_hhi[M_ * F_], g_hlo[M_ * F_];
__device__ u16 g_wq[QKV_ * D_];
__device__ u16 g_wo[D_ * D_];
__device__ u16 g_w1[F_ * D_];
__device__ u16 g_w2[D_ * F_];
__device__ u16 g_hw[V_ * D_];

// ---------------- fp16 split helpers ----------------
__device__ __forceinline__ u16 f16_hi(float v) {
    __half h = __float2half_rn(v);
    return *(u16*)&h;
}
__device__ __forceinline__ u16 f16_lo(float v) {
    __half h = __float2half_rn(v);
    float r = v - __half2float(h);
    __half l = __float2half_rn(r);
    return *(u16*)&l;
}
__device__ __forceinline__ uint32_t packh2(float a, float b) {
    __half2 t = __halves2half2(__float2half_rn(a), __float2half_rn(b));
    return *(uint32_t*)&t;
}
__device__ __forceinline__ uint32_t packh2_lo(float a, float b) {
    float ra = a - __half2float(__float2half_rn(a));
    float rb = b - __half2float(__float2half_rn(b));
    return packh2(ra, rb);
}

__device__ __forceinline__ uint32_t smem_u32(const void* p) {
    uint32_t a;
    asm("{ .reg .u64 t; cvta.to.shared.u64 t, %1; cvt.u32.u64 %0, t; }"
        : "=r"(a) : "l"(p));
    return a;
}

#define LDSM4(r, addr)                                                          \
    asm volatile("ldmatrix.sync.aligned.m8n8.x4.shared.b16 {%0,%1,%2,%3}, [%4];" \
                 : "=r"((r)[0]), "=r"((r)[1]), "=r"((r)[2]), "=r"((r)[3])        \
                 : "r"(addr))
#define LDSM2(r, addr)                                                          \
    asm volatile("ldmatrix.sync.aligned.m8n8.x2.shared.b16 {%0,%1}, [%2];"       \
                 : "=r"((r)[0]), "=r"((r)[1]) : "r"(addr))
#define MMAH(c, a, b)                                                           \
    asm volatile("mma.sync.aligned.m16n8k16.row.col.f32.f16.f16.f32 "            \
                 "{%0,%1,%2,%3}, {%4,%5,%6,%7}, {%8,%9}, {%0,%1,%2,%3};"         \
                 : "+f"((c)[0]), "+f"((c)[1]), "+f"((c)[2]), "+f"((c)[3])        \
                 : "r"((a)[0]), "r"((a)[1]), "r"((a)[2]), "r"((a)[3]),           \
                   "r"((b)[0]), "r"((b)[1]))

// ==================== fp16 mma.sync GEMM (2-pass split-A) ====================
#define KSTRIDE 40
#define MAT_B  (128 * KSTRIDE * 2)
#define AH_OFF 0
#define AL_OFF (1 * MAT_B)
#define BH_OFF (2 * MAT_B)
#define STG_B  (3 * MAT_B)
#define NSTG   4
#define SMEM_GEMM (NSTG * STG_B)   // 122880 B

#define CP16(s, g)  asm volatile("cp.async.cg.shared.global [%0], [%1], 16;" :: "r"(s), "l"(g))
#define CP_COMMIT() asm volatile("cp.async.commit_group;" ::: "memory")
#define CP_WAIT2()  asm volatile("cp.async.wait_group 2;" ::: "memory")

template <bool SPLIT_OUT>
__global__ __launch_bounds__(256)
void gemm_f16(const u16* __restrict__ Ahi, const u16* __restrict__ Alo,
              const u16* __restrict__ Bh,
              const float* __restrict__ bias, float* __restrict__ Cf,
              u16* __restrict__ Chi, u16* __restrict__ Clo,
              int M, int N, int K, int relu) {
    extern __shared__ char sm[];
    uint32_t sb = smem_u32(sm);
    int tid = threadIdx.x, wid = tid >> 5, lane = tid & 31;
    int bm = blockIdx.y * 128, bn = blockIdx.x * 128;
    int warp_m = (wid & 1) * 64, warp_n = (wid >> 1) * 32;

    uint32_t a_off = (uint32_t)(warp_m + (lane & 15)) * KSTRIDE + ((lane >> 4) << 3);
    uint32_t b_off = (uint32_t)(warp_n + (lane & 7)) * KSTRIDE + (((lane >> 3) & 1) << 3);

    int c0i = tid * 2;
    int lrow0 = c0i >> 2, lc0 = (c0i & 3);
    int lrow1 = (c0i + 1) >> 2, lc1 = ((c0i + 1) & 3);

    float acc[4][4][4];
#pragma unroll
    for (int mi = 0; mi < 4; mi++)
#pragma unroll
        for (int ni = 0; ni < 4; ni++)
#pragma unroll
            for (int f = 0; f < 4; f++) acc[mi][ni][f] = 0.0f;

    int nt = K >> 5;

    auto load_stage = [&](int stg, int t) {
        uint32_t ss = sb + (uint32_t)stg * STG_B;
        int k0 = t << 5;
        uint32_t s0 = lrow0 * (KSTRIDE * 2) + lc0 * 16;
        uint32_t s1 = lrow1 * (KSTRIDE * 2) + lc1 * 16;
        size_t ga0 = (size_t)(bm + lrow0) * K + k0 + lc0 * 8;
        size_t ga1 = (size_t)(bm + lrow1) * K + k0 + lc1 * 8;
        size_t gb0 = (size_t)(bn + lrow0) * K + k0 + lc0 * 8;
        size_t gb1 = (size_t)(bn + lrow1) * K + k0 + lc1 * 8;
        CP16(ss + AH_OFF + s0, &Ahi[ga0]);
        CP16(ss + AH_OFF + s1, &Ahi[ga1]);
        CP16(ss + AL_OFF + s0, &Alo[ga0]);
        CP16(ss + AL_OFF + s1, &Alo[ga1]);
        CP16(ss + BH_OFF + s0, &Bh[gb0]);
        CP16(ss + BH_OFF + s1, &Bh[gb1]);
    };

#pragma unroll
    for (int s = 0; s < NSTG - 1; s++) {
        if (s < nt) load_stage(s, s);
        CP_COMMIT();
    }

    for (int t = 0; t < nt; t++) {
        CP_WAIT2();
        __syncthreads();

        uint32_t sa = sb + (uint32_t)(t & (NSTG - 1)) * STG_B;
#pragma unroll
        for (int ks = 0; ks < 2; ks++) {
            uint32_t aoff2 = (a_off + ks * 16) * 2;
            uint32_t boff2 = (b_off + ks * 16) * 2;
            uint32_t ah[4][4], al[4][4], bh[4][2];
#pragma unroll
            for (int mi = 0; mi < 4; mi++)
                LDSM4(ah[mi], sa + AH_OFF + aoff2 + mi * (16 * KSTRIDE * 2));
#pragma unroll
            for (int ni = 0; ni < 4; ni++)
                LDSM2(bh[ni], sa + BH_OFF + boff2 + ni * (8 * KSTRIDE * 2));
#pragma unroll
            for (int mi = 0; mi < 4; mi++)
#pragma unroll
                for (int ni = 0; ni < 4; ni++) MMAH(acc[mi][ni], ah[mi], bh[ni]);
#pragma unroll
            for (int mi = 0; mi < 4; mi++)
                LDSM4(al[mi], sa + AL_OFF + aoff2 + mi * (16 * KSTRIDE * 2));
#pragma unroll
            for (int mi = 0; mi < 4; mi++)
#pragma unroll
                for (int ni = 0; ni < 4; ni++) MMAH(acc[mi][ni], al[mi], bh[ni]);
        }

        if (t + NSTG - 1 < nt) load_stage((t + NSTG - 1) & (NSTG - 1), t + NSTG - 1);
        CP_COMMIT();
    }

    int gid = lane >> 2, tig = lane & 3;
#pragma unroll
    for (int mi = 0; mi < 4; mi++) {
        int r0 = bm + warp_m + mi * 16 + gid;
#pragma unroll
        for (int ni = 0; ni < 4; ni++) {
            int cg = bn + warp_n + ni * 8 + tig * 2;
            float c0 = acc[mi][ni][0], c1 = acc[mi][ni][1];
            float c2 = acc[mi][ni][2], c3 = acc[mi][ni][3];
            if (bias) {
                float bx = bias[cg], by = bias[cg + 1];
                c0 += bx; c1 += by; c2 += bx; c3 += by;
            }
            if (relu) {
                c0 = fmaxf(c0, 0.0f); c1 = fmaxf(c1, 0.0f);
                c2 = fmaxf(c2, 0.0f); c3 = fmaxf(c3, 0.0f);
            }
            if (SPLIT_OUT) {
                size_t i0 = (size_t)r0 * N + cg, i1 = (size_t)(r0 + 8) * N + cg;
                *(uint32_t*)&Chi[i0] = (uint32_t)f16_hi(c0) | ((uint32_t)f16_hi(c1) << 16);
                *(uint32_t*)&Clo[i0] = (uint32_t)f16_lo(c0) | ((uint32_t)f16_lo(c1) << 16);
                *(uint32_t*)&Chi[i1] = (uint32_t)f16_hi(c2) | ((uint32_t)f16_hi(c3) << 16);
                *(uint32_t*)&Clo[i1] = (uint32_t)f16_lo(c2) | ((uint32_t)f16_lo(c3) << 16);
            } else {
                *(float2*)&Cf[(size_t)r0 * N + cg] = make_float2(c0, c1);
                *(float2*)&Cf[(size_t)(r0 + 8) * N + cg] = make_float2(c2, c3);
            }
        }
    }
}

// ==================== tensor-core causal attention ====================
// grid (S/64, B*H), 128 threads (4 warps x 16 queries).
// QK^T: 3-pass split-f16; softmax on fp32 frags; P@V: 3-pass, V transposed.
#define QSTR 72
#define ATT_MAT (64 * QSTR)                 // u16 elems per buffer
#define SMEM_ATT (6 * ATT_MAT * 2)          // 55296 B

__global__ __launch_bounds__(128)
void attn_tc(const float* __restrict__ qkv,
             u16* __restrict__ ohi, u16* __restrict__ olo) {
    extern __shared__ u16 sm16[];
    u16* Qh = sm16;
    u16* Ql = Qh + ATT_MAT;
    u16* Kh = Ql + ATT_MAT;
    u16* Kl = Kh + ATT_MAT;
    u16* Vh = Kl + ATT_MAT;
    u16* Vl = Vh + ATT_MAT;
    uint32_t sQh = smem_u32(Qh), sQl = smem_u32(Ql);
    uint32_t sKh = smem_u32(Kh), sKl = smem_u32(Kl);
    uint32_t sVh = smem_u32(Vh), sVl = smem_u32(Vl);

    int tid = threadIdx.x, wid = tid >> 5, lane = tid & 31;
    int gid = lane >> 2, tig = lane & 3;
    int bh = blockIdx.y;
    int b = bh / H_, h = bh % H_;
    int q0 = blockIdx.x * 64;

    const float* qp = qkv + (size_t)(b * S_ + q0) * QKV_ + h * HD_;

    // stage Q (64x64 -> hi/lo f16)
    for (int i = tid; i < 64 * 16; i += 128) {
        int r = i >> 4, c4 = (i & 15) * 4;
        float4 v = *(const float4*)&qp[(size_t)r * QKV_ + c4];
        uint32_t* dh = (uint32_t*)&Qh[r * QSTR + c4];
        uint32_t* dl = (uint32_t*)&Ql[r * QSTR + c4];
        dh[0] = packh2(v.x, v.y); dh[1] = packh2(v.z, v.w);
        dl[0] = packh2_lo(v.x, v.y); dl[1] = packh2_lo(v.z, v.w);
    }

    int warp_m = wid * 16;
    uint32_t qa_off = (uint32_t)(warp_m + (lane & 15)) * QSTR + ((lane >> 4) << 3);
    uint32_t kb_off = (uint32_t)(lane & 7) * QSTR + (((lane >> 3) & 1) << 3);

    uint32_t qh[4][4], ql[4][4];
    float m0 = -1e30f, m1 = -1e30f, l0 = 0.0f, l1 = 0.0f;
    float O[8][4];
#pragma unroll
    for (int n = 0; n < 8; n++)
#pragma unroll
        for (int f = 0; f < 4; f++) O[n][f] = 0.0f;

    int ntiles = blockIdx.x + 1;
    const float sc = 0.125f;

    for (int t = 0; t < ntiles; t++) {
        // stage K (rows=key, cols=hd) and V transposed (rows=hd, cols=key)
        const float* kp = qkv + (size_t)(b * S_ + t * 64) * QKV_ + D_ + h * HD_;
        const float* vp = qkv + (size_t)(b * S_ + t * 64) * QKV_ + 2 * D_ + h * HD_;
        for (int i = tid; i < 64 * 16; i += 128) {
            int r = i >> 4, c4 = (i & 15) * 4;
            float4 kv = *(const float4*)&kp[(size_t)r * QKV_ + c4];
            uint32_t* dh = (uint32_t*)&Kh[r * QSTR + c4];
            uint32_t* dl = (uint32_t*)&Kl[r * QSTR + c4];
            dh[0] = packh2(kv.x, kv.y); dh[1] = packh2(kv.z, kv.w);
            dl[0] = packh2_lo(kv.x, kv.y); dl[1] = packh2_lo(kv.z, kv.w);
            float4 vv = *(const float4*)&vp[(size_t)r * QKV_ + c4];
            Vh[(c4 + 0) * QSTR + r] = f16_hi(vv.x); Vl[(c4 + 0) * QSTR + r] = f16_lo(vv.x);
            Vh[(c4 + 1) * QSTR + r] = f16_hi(vv.y); Vl[(c4 + 1) * QSTR + r] = f16_lo(vv.y);
            Vh[(c4 + 2) * QSTR + r] = f16_hi(vv.z); Vl[(c4 + 2) * QSTR + r] = f16_lo(vv.z);
            Vh[(c4 + 3) * QSTR + r] = f16_hi(vv.w); Vl[(c4 + 3) * QSTR + r] = f16_lo(vv.w);
        }
        __syncthreads();

        if (t == 0) {
#pragma unroll
            for (int ks = 0; ks < 4; ks++) {
                LDSM4(qh[ks], sQh + (qa_off + ks * 16) * 2);
                LDSM4(ql[ks], sQl + (qa_off + ks * 16) * 2);
            }
        }

        // scores S = Q K^T (3 passes)
        float s[8][4];
#pragma unroll
        for (int n = 0; n < 8; n++) {
#pragma unroll
            for (int f = 0; f < 4; f++) s[n][f] = 0.0f;
#pragma unroll
            for (int ks = 0; ks < 4; ks++) {
                uint32_t kh2[2], kl2[2];
                uint32_t ko = (kb_off + (uint32_t)n * 8 * QSTR + ks * 16) * 2;
                LDSM2(kh2, sKh + ko);
                LDSM2(kl2, sKl + ko);
                MMAH(s[n], qh[ks], kh2);
                MMAH(s[n], ql[ks], kh2);
                MMAH(s[n], qh[ks], kl2);
            }
        }

        // scale + causal mask (diag tile only)
        int ql0 = warp_m + gid, ql1 = ql0 + 8;
#pragma unroll
        for (int n = 0; n < 8; n++) {
            s[n][0] *= sc; s[n][1] *= sc; s[n][2] *= sc; s[n][3] *= sc;
            if (t == blockIdx.x) {
                int kc = n * 8 + 2 * tig;
                if (kc > ql0) s[n][0] = -1e30f;
                if (kc + 1 > ql0) s[n][1] = -1e30f;
                if (kc > ql1) s[n][2] = -1e30f;
                if (kc + 1 > ql1) s[n][3] = -1e30f;
            }
        }

        // row max across 4-lane group
        float tm0 = -1e30f, tm1 = -1e30f;
#pragma unroll
        for (int n = 0; n < 8; n++) {
            tm0 = fmaxf(tm0, fmaxf(s[n][0], s[n][1]));
            tm1 = fmaxf(tm1, fmaxf(s[n][2], s[n][3]));
        }
        tm0 = fmaxf(tm0, __shfl_xor_sync(0xFFFFFFFF, tm0, 1));
        tm0 = fmaxf(tm0, __shfl_xor_sync(0xFFFFFFFF, tm0, 2));
        tm1 = fmaxf(tm1, __shfl_xor_sync(0xFFFFFFFF, tm1, 1));
        tm1 = fmaxf(tm1, __shfl_xor_sync(0xFFFFFFFF, tm1, 2));

        float mn0 = fmaxf(m0, tm0), mn1 = fmaxf(m1, tm1);
        float corr0 = __expf(m0 - mn0), corr1 = __expf(m1 - mn1);
        m0 = mn0; m1 = mn1;

        float sum0 = 0.0f, sum1 = 0.0f;
#pragma unroll
        for (int n = 0; n < 8; n++) {
            s[n][0] = __expf(s[n][0] - mn0);
            s[n][1] = __expf(s[n][1] - mn0);
            s[n][2] = __expf(s[n][2] - mn1);
            s[n][3] = __expf(s[n][3] - mn1);
            sum0 += s[n][0] + s[n][1];
            sum1 += s[n][2] + s[n][3];
        }
        sum0 += __shfl_xor_sync(0xFFFFFFFF, sum0, 1);
        sum0 += __shfl_xor_sync(0xFFFFFFFF, sum0, 2);
        sum1 += __shfl_xor_sync(0xFFFFFFFF, sum1, 1);
        sum1 += __shfl_xor_sync(0xFFFFFFFF, sum1, 2);
        l0 = l0 * corr0 + sum0;
        l1 = l1 * corr1 + sum1;

#pragma unroll
        for (int n = 0; n < 8; n++) {
            O[n][0] *= corr0; O[n][1] *= corr0;
            O[n][2] *= corr1; O[n][3] *= corr1;
        }

        // pack P into A-fragments (hi + residual lo)
        uint32_t ph[8][2], pl[8][2];
#pragma unroll
        for (int n = 0; n < 8; n++) {
            ph[n][0] = packh2(s[n][0], s[n][1]);
            ph[n][1] = packh2(s[n][2], s[n][3]);
            pl[n][0] = packh2_lo(s[n][0], s[n][1]);
            pl[n][1] = packh2_lo(s[n][2], s[n][3]);
        }

        // O += P V  (3 passes)
#pragma unroll
        for (int n = 0; n < 8; n++) {        // hd n-tiles
#pragma unroll
            for (int kt = 0; kt < 4; kt++) { // 16-key k-steps
                uint32_t vh2[2], vl2[2];
                uint32_t vo = (kb_off + (uint32_t)n * 8 * QSTR + kt * 16) * 2;
                LDSM2(vh2, sVh + vo);
                LDSM2(vl2, sVl + vo);
                uint32_t aH[4] = {ph[2 * kt][0], ph[2 * kt][1],
                                  ph[2 * kt + 1][0], ph[2 * kt + 1][1]};
                uint32_t aL[4] = {pl[2 * kt][0], pl[2 * kt][1],
                                  pl[2 * kt + 1][0], pl[2 * kt + 1][1]};
                MMAH(O[n], aH, vh2);
                MMAH(O[n], aL, vh2);
                MMAH(O[n], aH, vl2);
            }
        }
        __syncthreads();
    }

    float inv0 = 1.0f / l0, inv1 = 1.0f / l1;
    int r0 = b * S_ + q0 + warp_m + gid;
#pragma unroll
    for (int n = 0; n < 8; n++) {
        float o0 = O[n][0] * inv0, o1 = O[n][1] * inv0;
        float o2 = O[n][2] * inv1, o3 = O[n][3] * inv1;
        size_t i0 = (size_t)r0 * D_ + h * HD_ + n * 8 + 2 * tig;
        size_t i1 = (size_t)(r0 + 8) * D_ + h * HD_ + n * 8 + 2 * tig;
        *(uint32_t*)&ohi[i0] = (uint32_t)f16_hi(o0) | ((uint32_t)f16_hi(o1) << 16);
        *(uint32_t*)&olo[i0] = (uint32_t)f16_lo(o0) | ((uint32_t)f16_lo(o1) << 16);
        *(uint32_t*)&ohi[i1] = (uint32_t)f16_hi(o2) | ((uint32_t)f16_hi(o3) << 16);
        *(uint32_t*)&olo[i1] = (uint32_t)f16_lo(o2) | ((uint32_t)f16_lo(o3) << 16);
    }
}

// ---------------- embedding + PE (+ split) ----------------
__global__ void embed_kernel(const int* __restrict__ tokens,
                             const float* __restrict__ emb,
                             float* __restrict__ x,
                             u16* __restrict__ xhi, u16* __restrict__ xlo) {
    int i = blockIdx.x * blockDim.x + threadIdx.x;
    if (i >= M_ * D_) return;
    int m = i / D_, d = i % D_;
    int s = m % S_;
    int tok = tokens[m];
    float expo = (float)(d & ~1) * (-logf(10000.0f) / (float)D_);
    float ang = (float)s * expf(expo);
    float pe = (d & 1) ? cosf(ang) : sinf(ang);
    float v = emb[tok * D_ + d] + pe;
    x[i] = v;
    xhi[i] = f16_hi(v);
    xlo[i] = f16_lo(v);
}

// ---------------- repack QKV weights -> [3D][D] fp16 ----------------
__global__ void repack_qkvT_h(const float* __restrict__ Wq,
                              const float* __restrict__ Wk,
                              const float* __restrict__ Wv,
                              u16* __restrict__ w) {
    int i = blockIdx.x * blockDim.x + threadIdx.x;
    if (i >= D_ * D_) return;
    int n = i / D_, d = i % D_;
    int h = n / HD_, e = n % HD_;
    int src = h * D_ * HD_ + d * HD_ + e;
    size_t iq = (size_t)n * D_ + d;
    w[iq] = f16_hi(Wq[src]);
    w[iq + (size_t)D_ * D_] = f16_hi(Wk[src]);
    w[iq + (size_t)2 * D_ * D_] = f16_hi(Wv[src]);
}

// ---------------- transpose to fp16 ----------------
__global__ void transpose_h(const float* __restrict__ in,
                            u16* __restrict__ o, int R, int C) {
    __shared__ float tile[32][33];
    int c0 = blockIdx.x * 32, r0 = blockIdx.y * 32;
    int x = threadIdx.x, y = threadIdx.y;
#pragma unroll
    for (int i = 0; i < 32; i += 8)
        tile[y + i][x] = in[(size_t)(r0 + y + i) * C + c0 + x];
    __syncthreads();
#pragma unroll
    for (int i = 0; i < 32; i += 8)
        o[(size_t)(c0 + y + i) * R + r0 + x] = f16_hi(tile[x][y + i]);
}

// ---------------- plain fp16 convert (head_W) ----------------
__global__ void conv_h(const float* __restrict__ in, u16* __restrict__ o, int n) {
    int i = blockIdx.x * blockDim.x + threadIdx.x;
    if (i >= n) return;
    o[i] = f16_hi(in[i]);
}

// ---------------- residual + LayerNorm (+ split) ----------------
__global__ __launch_bounds__(128)
void ln_kernel(float* __restrict__ x, const float* __restrict__ delta,
               const float* __restrict__ gamma, const float* __restrict__ beta,
               u16* __restrict__ xhi, u16* __restrict__ xlo) {
    int row = blockIdx.x;
    int tid = threadIdx.x;
    __shared__ float red[128];

    float v[4];
    float s = 0.0f;
#pragma unroll
    for (int i = 0; i < 4; i++) {
        int d = i * 128 + tid;
        float t = x[(size_t)row * D_ + d];
        if (delta) t += delta[(size_t)row * D_ + d];
        v[i] = t;
        s += t;
    }
    red[tid] = s;
    __syncthreads();
    for (int off = 64; off > 0; off >>= 1) {
        if (tid < off) red[tid] += red[tid + off];
        __syncthreads();
    }
    float mean = red[0] * (1.0f / D_);
    __syncthreads();

    float s2 = 0.0f;
#pragma unroll
    for (int i = 0; i < 4; i++) {
        float dv = v[i] - mean;
        s2 += dv * dv;
    }
    red[tid] = s2;
    __syncthreads();
    for (int off = 64; off > 0; off >>= 1) {
        if (tid < off) red[tid] += red[tid + off];
        __syncthreads();
    }
    float var = red[0] * (1.0f / D_);
    float rstd = rsqrtf(var + 1e-5f);
#pragma unroll
    for (int i = 0; i < 4; i++) {
        int d = i * 128 + tid;
        float o = (v[i] - mean) * rstd * gamma[d] + beta[d];
        size_t idx = (size_t)row * D_ + d;
        x[idx] = o;
        xhi[idx] = f16_hi(o);
        xlo[idx] = f16_lo(o);
    }
}

// ---------------- launch ----------------
extern "C" void kernel_launch(void* const* d_in, const int* in_sizes, int n_in,
                              void* d_out, int out_size) {
    const int* tokens    = (const int*)d_in[0];
    const float* emb     = (const float*)d_in[1];
    const float* Wq      = (const float*)d_in[2];
    const float* Wk      = (const float*)d_in[3];
    const float* Wv      = (const float*)d_in[4];
    const float* Wo      = (const float*)d_in[5];
    const float* bo      = (const float*)d_in[6];
    const float* ln1_g   = (const float*)d_in[7];
    const float* ln1_b   = (const float*)d_in[8];
    const float* W1      = (const float*)d_in[9];
    const float* b1      = (const float*)d_in[10];
    const float* W2      = (const float*)d_in[11];
    const float* b2      = (const float*)d_in[12];
    const float* ln2_g   = (const float*)d_in[13];
    const float* ln2_b   = (const float*)d_in[14];
    const float* lnf_g   = (const float*)d_in[15];
    const float* lnf_b   = (const float*)d_in[16];
    const float* head_W  = (const float*)d_in[17];
    float* out = (float*)d_out;

    float *x, *qkv, *t;
    u16 *xhi, *xlo, *ohi, *olo, *hhi, *hlo;
    u16 *wq, *wo, *w1, *w2, *hw;
    cudaGetSymbolAddress((void**)&x, g_x);
    cudaGetSymbolAddress((void**)&qkv, g_qkv);
    cudaGetSymbolAddress((void**)&t, g_t);
    cudaGetSymbolAddress((void**)&xhi, g_xhi);
    cudaGetSymbolAddress((void**)&xlo, g_xlo);
    cudaGetSymbolAddress((void**)&ohi, g_ohi);
    cudaGetSymbolAddress((void**)&olo, g_olo);
    cudaGetSymbolAddress((void**)&hhi, g_hhi);
    cudaGetSymbolAddress((void**)&hlo, g_hlo);
    cudaGetSymbolAddress((void**)&wq, g_wq);
    cudaGetSymbolAddress((void**)&wo, g_wo);
    cudaGetSymbolAddress((void**)&w1, g_w1);
    cudaGetSymbolAddress((void**)&w2, g_w2);
    cudaGetSymbolAddress((void**)&hw, g_hw);

    cudaFuncSetAttribute(gemm_f16<false>, cudaFuncAttributeMaxDynamicSharedMemorySize, SMEM_GEMM);
    cudaFuncSetAttribute(gemm_f16<true>,  cudaFuncAttributeMaxDynamicSharedMemorySize, SMEM_GEMM);
    cudaFuncSetAttribute(attn_tc, cudaFuncAttributeMaxDynamicSharedMemorySize, SMEM_ATT);

    embed_kernel<<<(M_ * D_ + 255) / 256, 256>>>(tokens, emb, x, xhi, xlo);
    conv_h<<<(V_ * D_ + 255) / 256, 256>>>(head_W, hw, V_ * D_);

    dim3 gQKV(QKV_ / 128, M_ / 128);
    dim3 gD(D_ / 128, M_ / 128);
    dim3 gF(F_ / 128, M_ / 128);
    dim3 gV(V_ / 128, M_ / 128);
    dim3 gAttn(S_ / 64, B_ * H_);
    dim3 tb(32, 8);

    for (int l = 0; l < L_; l++) {
        const float* Wq_l = Wq + (size_t)l * H_ * D_ * HD_;
        const float* Wk_l = Wk + (size_t)l * H_ * D_ * HD_;
        const float* Wv_l = Wv + (size_t)l * H_ * D_ * HD_;
        const float* Wo_l = Wo + (size_t)l * D_ * D_;
        const float* bo_l = bo + (size_t)l * D_;
        const float* W1_l = W1 + (size_t)l * D_ * F_;
        const float* b1_l = b1 + (size_t)l * F_;
        const float* W2_l = W2 + (size_t)l * F_ * D_;
        const float* b2_l = b2 + (size_t)l * D_;

        repack_qkvT_h<<<(D_ * D_ + 255) / 256, 256>>>(Wq_l, Wk_l, Wv_l, wq);
        transpose_h<<<dim3(D_ / 32, D_ / 32), tb>>>(Wo_l, wo, D_, D_);
        transpose_h<<<dim3(F_ / 32, D_ / 32), tb>>>(W1_l, w1, D_, F_);
        transpose_h<<<dim3(D_ / 32, F_ / 32), tb>>>(W2_l, w2, F_, D_);

        gemm_f16<false><<<gQKV, 256, SMEM_GEMM>>>(xhi, xlo, wq, nullptr,
                                                  qkv, nullptr, nullptr, M_, QKV_, D_, 0);

        attn_tc<<<gAttn, 128, SMEM_ATT>>>(qkv, ohi, olo);

        gemm_f16<false><<<gD, 256, SMEM_GEMM>>>(ohi, olo, wo, bo_l,
                                                t, nullptr, nullptr, M_, D_, D_, 0);
        ln_kernel<<<M_, 128>>>(x, t, ln1_g + (size_t)l * D_, ln1_b + (size_t)l * D_, xhi, xlo);

        gemm_f16<true><<<gF, 256, SMEM_GEMM>>>(xhi, xlo, w1, b1_l,
                                               nullptr, hhi, hlo, M_, F_, D_, 1);
        gemm_f16<false><<<gD, 256, SMEM_GEMM>>>(hhi, hlo, w2, b2_l,
                                                t, nullptr, nullptr, M_, D_, F_, 0);
        ln_kernel<<<M_, 128>>>(x, t, ln2_g + (size_t)l * D_, ln2_b + (size_t)l * D_, xhi, xlo);
    }

    ln_kernel<<<M_, 128>>>(x, nullptr, lnf_g, lnf_b, xhi, xlo);
    gemm_f16<false><<<gV, 256, SMEM_GEMM>>>(xhi, xlo, hw, nullptr,
                                            out, nullptr, nullptr, M_, V_, D_, 0);
}